// round 15
// baseline (speedup 1.0000x reference)
#include <cuda_runtime.h>
#include <cuda_fp16.h>
#include <cstdint>

#define N_NODES 50000
#define EMBED 128
#define HIDDEN 256
#define N_EDGES 640000
#define LN_EPS 1e-5f

// ---------------- warp MMA / cp.async helpers (sm_80-class) ----------------
__device__ __forceinline__ uint32_t smem_u32(const void* p) {
    uint32_t a;
    asm("{ .reg .u64 t; cvta.to.shared.u64 t, %1; cvt.u32.u64 %0, t; }"
        : "=r"(a) : "l"(p));
    return a;
}
__device__ __forceinline__ void mma_f16(float* d, const uint32_t* a, const uint32_t* b) {
    asm volatile(
        "mma.sync.aligned.m16n8k16.row.col.f32.f16.f16.f32 "
        "{%0,%1,%2,%3}, {%4,%5,%6,%7}, {%8,%9}, {%0,%1,%2,%3};"
        : "+f"(d[0]), "+f"(d[1]), "+f"(d[2]), "+f"(d[3])
        : "r"(a[0]), "r"(a[1]), "r"(a[2]), "r"(a[3]), "r"(b[0]), "r"(b[1]));
}
__device__ __forceinline__ void ldm4(uint32_t* r, uint32_t addr) {
    asm volatile("ldmatrix.sync.aligned.m8n8.x4.shared.b16 {%0,%1,%2,%3}, [%4];"
                 : "=r"(r[0]), "=r"(r[1]), "=r"(r[2]), "=r"(r[3]) : "r"(addr));
}
__device__ __forceinline__ void ldm2(uint32_t* r, uint32_t addr) {
    asm volatile("ldmatrix.sync.aligned.m8n8.x2.shared.b16 {%0,%1}, [%2];"
                 : "=r"(r[0]), "=r"(r[1]) : "r"(addr));
}
__device__ __forceinline__ void cpa16(uint32_t dst, const void* src) {
    asm volatile("cp.async.cg.shared.global [%0], [%1], 16;" :: "r"(dst), "l"(src));
}
#define CP_COMMIT() asm volatile("cp.async.commit_group;" ::: "memory")
#define CP_WAIT(n)  asm volatile("cp.async.wait_group %0;" :: "n"(n) : "memory")

__device__ __forceinline__ float silu_f(float x) {
    return __fdividef(x, 1.0f + __expf(-x));
}

// ---------------- device scratch ----------------
__device__ float g_h[N_NODES * EMBED];     // layernormed node embeddings
__device__ float g_agg[N_NODES * EMBED];   // init to h; edge atomics add msg -> h+agg
__device__ __align__(16) __half g_w1h[32768];   // W1^T [n=256][k=128]
__device__ __align__(16) __half g_w2h[32768];   // W2^T [n=128][kk=256]
__device__ __align__(16) __half g_wth[16384];   // Wt^T [n=128][k=128]

// ---------------------------------------------------------------------------
// Kernel 1 (fused): blocks 0..127 = weight prep; rest = LayerNorm (warp/row).
// ln writes h into BOTH g_h and g_agg (so edge atomics accumulate onto h).
// ---------------------------------------------------------------------------
#define PREP_BLOCKS 128

__global__ void init_kernel(const float* __restrict__ x,
                            const float* __restrict__ gamma,
                            const float* __restrict__ beta,
                            const float* __restrict__ W1,
                            const float* __restrict__ W2,
                            const float* __restrict__ Wt) {
    if (blockIdx.x < PREP_BLOCKS) {
        int idx = blockIdx.x * blockDim.x + threadIdx.x;   // 0..32767
        {   int k = idx >> 8, n = idx & 255;
            g_w1h[n * 128 + k] = __float2half_rn(W1[idx]); }
        {   int kk = idx >> 7, n = idx & 127;
            g_w2h[n * 256 + kk] = __float2half_rn(W2[idx]); }
        if (idx < 16384) {
            int k = idx >> 7, n = idx & 127;
            g_wth[n * 128 + k] = __float2half_rn(Wt[idx]);
        }
        return;
    }

    int warp = ((blockIdx.x - PREP_BLOCKS) * blockDim.x + threadIdx.x) >> 5;
    int lane = threadIdx.x & 31;
    if (warp >= N_NODES) return;

    const float4* row = (const float4*)(x + (size_t)warp * EMBED);
    float4 v = row[lane];
    float s  = v.x + v.y + v.z + v.w;
    float ss = v.x * v.x + v.y * v.y + v.z * v.z + v.w * v.w;
    #pragma unroll
    for (int o = 16; o; o >>= 1) {
        s  += __shfl_xor_sync(0xFFFFFFFFu, s,  o);
        ss += __shfl_xor_sync(0xFFFFFFFFu, ss, o);
    }
    const float inv_d = 1.0f / (float)EMBED;
    float mu  = s * inv_d;
    float var = ss * inv_d - mu * mu;
    float inv = rsqrtf(var + LN_EPS);

    float4 g = ((const float4*)gamma)[lane];
    float4 b = ((const float4*)beta)[lane];
    float4 o4;
    o4.x = (v.x - mu) * inv * g.x + b.x;
    o4.y = (v.y - mu) * inv * g.y + b.y;
    o4.z = (v.z - mu) * inv * g.z + b.z;
    o4.w = (v.w - mu) * inv * g.w + b.w;
    ((float4*)(g_h + (size_t)warp * EMBED))[lane] = o4;
    ((float4*)(g_agg + (size_t)warp * EMBED))[lane] = o4;   // agg starts at h
}

// ---------------------------------------------------------------------------
// Kernel 2: fp16 mma.sync edge MLP. 128 edges/CTA, 8 warps, 2 CTAs/SM.
// Gather batched 2 rounds x 8 slots (24 loads in flight).
// ---------------------------------------------------------------------------
#define TE 128
#define ETH 256
#define A_STRIDE 264   // halves; 528B rows -> 16B-rotating, ldmatrix conflict-free
#define B_STRIDE 136   // halves; 272B rows

#define SM_CI   0
#define SM_NI   512
#define SM_B1   1024
#define SM_B2   2048
#define SM_A    2560
#define SM_B    (SM_A + 128 * A_STRIDE * 2)   // 70144
#define EDGE_SMEM (SM_B + 128 * B_STRIDE * 2) // 104960  -> 2 CTAs/SM

__device__ __forceinline__ void cp_tile(uint32_t sdst,
                                        const __half* __restrict__ src,
                                        int src_stride_halves, int tid) {
    #pragma unroll
    for (int i = tid; i < 2048; i += ETH) {
        int r = i >> 4, c = i & 15;
        cpa16(sdst + r * (B_STRIDE * 2) + c * 16,
              src + r * src_stride_halves + c * 8);
    }
}

__global__ __launch_bounds__(ETH, 2)
void edge_kernel(const float* __restrict__ eemb,
                 const int* __restrict__ eidx,
                 const float* __restrict__ b1g,
                 const float* __restrict__ b2g) {
    extern __shared__ char smem[];
    uint32_t sbase = smem_u32(smem);
    int tid = threadIdx.x, wid = tid >> 5, lane = tid & 31;
    int e0 = blockIdx.x * TE;

    int*   s_ci = (int*)(smem + SM_CI);
    int*   s_ni = (int*)(smem + SM_NI);
    float* sb1  = (float*)(smem + SM_B1);
    float* sb2  = (float*)(smem + SM_B2);

    cp_tile(sbase + SM_B, g_w1h, 128, tid); CP_COMMIT();

    if (tid < 128) {
        s_ci[tid] = eidx[e0 + tid];
        s_ni[tid] = eidx[N_EDGES + e0 + tid];
    }
    sb1[tid] = b1g[tid];
    if (tid < 128) sb2[tid] = b2g[tid];
    __syncthreads();

    // ---- gather: A1 = fp16(silu(e + h_c + h_n)), batched 2 rounds x 8 slots ----
    #pragma unroll
    for (int bt = 0; bt < 2; bt++) {
        float4 ee[8], hc[8], hn[8];
        #pragma unroll
        for (int j = 0; j < 8; j++) {
            int v = tid + ETH * (bt * 8 + j);   // 0..4095
            int m = v >> 5, c = v & 31;
            ee[j] = ((const float4*)(eemb + (size_t)(e0 + m) * EMBED))[c];
            hc[j] = ((const float4*)(g_h + (size_t)s_ci[m] * EMBED))[c];
            hn[j] = ((const float4*)(g_h + (size_t)s_ni[m] * EMBED))[c];
        }
        #pragma unroll
        for (int j = 0; j < 8; j++) {
            int v = tid + ETH * (bt * 8 + j);
            int m = v >> 5, c = v & 31;
            float s0 = silu_f(ee[j].x + hc[j].x + hn[j].x);
            float s1 = silu_f(ee[j].y + hc[j].y + hn[j].y);
            float s2 = silu_f(ee[j].z + hc[j].z + hn[j].z);
            float s3 = silu_f(ee[j].w + hc[j].w + hn[j].w);
            int off = (m * A_STRIDE + 4 * c) * 2;
            *(__half2*)(smem + SM_A + off)     = __floats2half2_rn(s0, s1);
            *(__half2*)(smem + SM_A + off + 4) = __floats2half2_rn(s2, s3);
        }
    }

    int rb = wid * 16;
    int ai = lane & 7, as_ = lane >> 3;
    int arow = rb + ai + (as_ & 1) * 8;
    int acolseg = (as_ >> 1) * 8;
    int bi = lane & 7, bs = (lane >> 3) & 1;
    int q = lane & 3;
    int r0 = rb + (lane >> 2), r1 = r0 + 8;

    // ================= GEMM1 (two n-halves) =================
    #pragma unroll 1
    for (int h = 0; h < 2; h++) {
        CP_WAIT(0);
        __syncthreads();

        float acc[16][4];
        #pragma unroll
        for (int i = 0; i < 16; i++)
            #pragma unroll
            for (int j = 0; j < 4; j++) acc[i][j] = 0.f;

        #pragma unroll
        for (int ks = 0; ks < 8; ks++) {
            uint32_t a4[4];
            uint32_t aoff = (uint32_t)(arow * A_STRIDE + ks * 16 + acolseg) * 2;
            ldm4(a4, sbase + SM_A + aoff);
            #pragma unroll
            for (int nt = 0; nt < 16; nt++) {
                uint32_t boff = (uint32_t)((nt * 8 + bi) * B_STRIDE + ks * 16 + bs * 8) * 2;
                uint32_t bw[2];
                ldm2(bw, sbase + SM_B + boff);
                mma_f16(acc[nt], a4, bw);
            }
        }
        __syncthreads();

        if (h == 0) { cp_tile(sbase + SM_B, g_w1h + 16384, 128, tid); CP_COMMIT(); }
        else        { cp_tile(sbase + SM_B, g_w2h,         256, tid); CP_COMMIT(); }

        int dbase = (h == 0) ? 128 : 0;
        #pragma unroll
        for (int nt = 0; nt < 16; nt++) {
            int c0 = nt * 8 + 2 * q;
            int gc = h * 128 + c0;
            float t0 = silu_f(acc[nt][0] + sb1[gc]);
            float t1 = silu_f(acc[nt][1] + sb1[gc + 1]);
            float t2 = silu_f(acc[nt][2] + sb1[gc]);
            float t3 = silu_f(acc[nt][3] + sb1[gc + 1]);
            int o0 = (r0 * A_STRIDE + dbase + c0) * 2;
            int o1 = (r1 * A_STRIDE + dbase + c0) * 2;
            *(__half2*)(smem + SM_A + o0) = __floats2half2_rn(t0, t1);
            *(__half2*)(smem + SM_A + o1) = __floats2half2_rn(t2, t3);
        }
    }

    // ================= GEMM2 (two k-phases) =============
    float acc2[16][4];
    #pragma unroll
    for (int i = 0; i < 16; i++)
        #pragma unroll
        for (int j = 0; j < 4; j++) acc2[i][j] = 0.f;

    #pragma unroll 1
    for (int ph = 0; ph < 2; ph++) {
        CP_WAIT(0);
        __syncthreads();

        int abase = (ph == 0) ? 128 : 0;
        #pragma unroll
        for (int ks = 0; ks < 8; ks++) {
            uint32_t a4[4];
            uint32_t aoff = (uint32_t)(arow * A_STRIDE + abase + ks * 16 + acolseg) * 2;
            ldm4(a4, sbase + SM_A + aoff);
            #pragma unroll
            for (int nt = 0; nt < 16; nt++) {
                uint32_t boff = (uint32_t)((nt * 8 + bi) * B_STRIDE + ks * 16 + bs * 8) * 2;
                uint32_t bw[2];
                ldm2(bw, sbase + SM_B + boff);
                mma_f16(acc2[nt], a4, bw);
            }
        }
        if (ph == 0) {
            __syncthreads();
            cp_tile(sbase + SM_B, g_w2h + 128, 256, tid); CP_COMMIT();
        }
    }

    // ---- epilogue ----
    {
        int ci0 = s_ci[r0], ci1 = s_ci[r1];
        int ni0 = s_ni[r0], ni1 = s_ni[r1];
        const float* hn0 = g_h + (size_t)ni0 * EMBED;
        const float* hn1 = g_h + (size_t)ni1 * EMBED;
        float* ag0 = g_agg + (size_t)ci0 * EMBED;
        float* ag1 = g_agg + (size_t)ci1 * EMBED;
        #pragma unroll
        for (int nt = 0; nt < 16; nt++) {
            int c0 = nt * 8 + 2 * q;
            float2 h0 = *(const float2*)(hn0 + c0);
            float2 h1 = *(const float2*)(hn1 + c0);
            atomicAdd(ag0 + c0,     (acc2[nt][0] + sb2[c0])     * h0.x);
            atomicAdd(ag0 + c0 + 1, (acc2[nt][1] + sb2[c0 + 1]) * h0.y);
            atomicAdd(ag1 + c0,     (acc2[nt][2] + sb2[c0])     * h1.x);
            atomicAdd(ag1 + c0 + 1, (acc2[nt][3] + sb2[c0 + 1]) * h1.y);
        }
    }
}

// ---------------------------------------------------------------------------
// Kernel 3: out = silu(g_agg) @ Wt + bt  (R13 version, 4 CTAs/SM)
// ---------------------------------------------------------------------------
#define ONR 64
#define OSM_BT  0
#define OSM_A   512
#define OSM_B   (OSM_A + ONR * B_STRIDE * 2)    // 17920
#define OUT_SMEM (OSM_B + 128 * B_STRIDE * 2)   // 52736

__device__ __forceinline__ void cp_tile_full(uint32_t sdst,
                                             const __half* __restrict__ src,
                                             int src_stride_halves, int tid) {
    #pragma unroll
    for (int i = tid; i < 2048; i += 256) {
        int r = i >> 4, c = i & 15;
        cpa16(sdst + r * (B_STRIDE * 2) + c * 16,
              src + r * src_stride_halves + c * 8);
    }
}

__global__ __launch_bounds__(256, 4)
void out_kernel(const float* __restrict__ btg, float* __restrict__ out) {
    extern __shared__ char smem[];
    uint32_t sbase = smem_u32(smem);
    int tid = threadIdx.x, wid = tid >> 5, lane = tid & 31;
    int n0 = blockIdx.x * ONR;

    float* sbt = (float*)(smem + OSM_BT);

    cp_tile_full(sbase + OSM_B, g_wth, 128, tid); CP_COMMIT();
    if (tid < 128) sbt[tid] = btg[tid];

    #pragma unroll
    for (int bt = 0; bt < 2; bt++) {
        float4 av[4];
        int mm[4], cc[4];
        #pragma unroll
        for (int j = 0; j < 4; j++) {
            int v = tid + 256 * (bt * 4 + j);   // 0..2047
            mm[j] = v >> 5; cc[j] = v & 31;
            int row = n0 + mm[j];
            av[j] = make_float4(0.f, 0.f, 0.f, 0.f);
            if (row < N_NODES)
                av[j] = ((const float4*)(g_agg + (size_t)row * EMBED))[cc[j]];
        }
        #pragma unroll
        for (int j = 0; j < 4; j++) {
            float s0 = silu_f(av[j].x);
            float s1 = silu_f(av[j].y);
            float s2 = silu_f(av[j].z);
            float s3 = silu_f(av[j].w);
            int off = (mm[j] * B_STRIDE + 4 * cc[j]) * 2;
            *(__half2*)(smem + OSM_A + off)     = __floats2half2_rn(s0, s1);
            *(__half2*)(smem + OSM_A + off + 4) = __floats2half2_rn(s2, s3);
        }
    }

    CP_WAIT(0);
    __syncthreads();

    int ai = lane & 7, as_ = lane >> 3;
    int arowoff = ai + (as_ & 1) * 8;
    int acolseg = (as_ >> 1) * 8;
    int bi = lane & 7, bs = (lane >> 3) & 1;
    int q = lane & 3;
    int nb = wid * 2;   // this warp's two n-tiles

    float acc[4][2][4];
    #pragma unroll
    for (int i = 0; i < 4; i++)
        #pragma unroll
        for (int t = 0; t < 2; t++)
            #pragma unroll
            for (int j = 0; j < 4; j++) acc[i][t][j] = 0.f;

    #pragma unroll
    for (int ks = 0; ks < 8; ks++) {
        uint32_t bw0[2], bw1[2];
        ldm2(bw0, sbase + OSM_B + (uint32_t)(((nb + 0) * 8 + bi) * B_STRIDE + ks * 16 + bs * 8) * 2);
        ldm2(bw1, sbase + OSM_B + (uint32_t)(((nb + 1) * 8 + bi) * B_STRIDE + ks * 16 + bs * 8) * 2);
        #pragma unroll
        for (int mb = 0; mb < 4; mb++) {
            uint32_t a4[4];
            uint32_t aoff = (uint32_t)((mb * 16 + arowoff) * B_STRIDE + ks * 16 + acolseg) * 2;
            ldm4(a4, sbase + OSM_A + aoff);
            mma_f16(acc[mb][0], a4, bw0);
            mma_f16(acc[mb][1], a4, bw1);
        }
    }

    #pragma unroll
    for (int mb = 0; mb < 4; mb++) {
        int row0 = n0 + mb * 16 + (lane >> 2);
        int row1 = row0 + 8;
        #pragma unroll
        for (int t = 0; t < 2; t++) {
            int c0 = (nb + t) * 8 + 2 * q;
            float2 b2 = *(const float2*)(sbt + c0);
            if (row0 < N_NODES) {
                float2 o0 = make_float2(acc[mb][t][0] + b2.x, acc[mb][t][1] + b2.y);
                *(float2*)(out + (size_t)row0 * EMBED + c0) = o0;
            }
            if (row1 < N_NODES) {
                float2 o1 = make_float2(acc[mb][t][2] + b2.x, acc[mb][t][3] + b2.y);
                *(float2*)(out + (size_t)row1 * EMBED + c0) = o1;
            }
        }
    }
}

// ---------------------------------------------------------------------------
extern "C" void kernel_launch(void* const* d_in, const int* in_sizes, int n_in,
                              void* d_out, int out_size) {
    const float* node  = (const float*)d_in[0];
    const float* eemb  = (const float*)d_in[1];
    const int*   eidx  = (const int*)  d_in[2];
    const float* gamma = (const float*)d_in[3];
    const float* beta  = (const float*)d_in[4];
    const float* W1    = (const float*)d_in[5];
    const float* b1    = (const float*)d_in[6];
    const float* W2    = (const float*)d_in[7];
    const float* b2    = (const float*)d_in[8];
    const float* Wt    = (const float*)d_in[9];
    const float* bt    = (const float*)d_in[10];
    float* out = (float*)d_out;

    cudaFuncSetAttribute(edge_kernel, cudaFuncAttributeMaxDynamicSharedMemorySize,
                         EDGE_SMEM);
    cudaFuncSetAttribute(out_kernel, cudaFuncAttributeMaxDynamicSharedMemorySize,
                         OUT_SMEM);

    init_kernel<<<PREP_BLOCKS + (N_NODES + 7) / 8, 256>>>(node, gamma, beta, W1, W2, Wt);
    edge_kernel<<<N_EDGES / TE, ETH, EDGE_SMEM>>>(eemb, eidx, b1, b2);
    out_kernel<<<(N_NODES + ONR - 1) / ONR, 256, OUT_SMEM>>>(bt, out);
}

// round 16
// speedup vs baseline: 1.0081x; 1.0081x over previous
#include <cuda_runtime.h>
#include <cuda_fp16.h>
#include <cstdint>

#define N_NODES 50000
#define EMBED 128
#define HIDDEN 256
#define N_EDGES 640000
#define LN_EPS 1e-5f

// ---------------- warp MMA / cp.async helpers (sm_80-class) ----------------
__device__ __forceinline__ uint32_t smem_u32(const void* p) {
    uint32_t a;
    asm("{ .reg .u64 t; cvta.to.shared.u64 t, %1; cvt.u32.u64 %0, t; }"
        : "=r"(a) : "l"(p));
    return a;
}
__device__ __forceinline__ void mma_f16(float* d, const uint32_t* a, const uint32_t* b) {
    asm volatile(
        "mma.sync.aligned.m16n8k16.row.col.f32.f16.f16.f32 "
        "{%0,%1,%2,%3}, {%4,%5,%6,%7}, {%8,%9}, {%0,%1,%2,%3};"
        : "+f"(d[0]), "+f"(d[1]), "+f"(d[2]), "+f"(d[3])
        : "r"(a[0]), "r"(a[1]), "r"(a[2]), "r"(a[3]), "r"(b[0]), "r"(b[1]));
}
__device__ __forceinline__ void ldm4(uint32_t* r, uint32_t addr) {
    asm volatile("ldmatrix.sync.aligned.m8n8.x4.shared.b16 {%0,%1,%2,%3}, [%4];"
                 : "=r"(r[0]), "=r"(r[1]), "=r"(r[2]), "=r"(r[3]) : "r"(addr));
}
__device__ __forceinline__ void ldm2(uint32_t* r, uint32_t addr) {
    asm volatile("ldmatrix.sync.aligned.m8n8.x2.shared.b16 {%0,%1}, [%2];"
                 : "=r"(r[0]), "=r"(r[1]) : "r"(addr));
}
__device__ __forceinline__ void cpa16(uint32_t dst, const void* src) {
    asm volatile("cp.async.cg.shared.global [%0], [%1], 16;" :: "r"(dst), "l"(src));
}
#define CP_COMMIT() asm volatile("cp.async.commit_group;" ::: "memory")
#define CP_WAIT(n)  asm volatile("cp.async.wait_group %0;" :: "n"(n) : "memory")

__device__ __forceinline__ float silu_f(float x) {
    return __fdividef(x, 1.0f + __expf(-x));
}

// ---------------- device scratch ----------------
__device__ float g_h[N_NODES * EMBED];     // layernormed node embeddings
__device__ float g_agg[N_NODES * EMBED];   // init to h; edge atomics add msg -> h+agg
__device__ __align__(16) __half g_w1h[32768];   // W1^T [n=256][k=128]
__device__ __align__(16) __half g_w2h[32768];   // W2^T [n=128][kk=256]
__device__ __align__(16) __half g_wth[16384];   // Wt^T [n=128][k=128]

// ---------------------------------------------------------------------------
// Kernel 1 (fused): blocks 0..127 = weight prep; rest = LayerNorm (warp/row).
// ln writes h into BOTH g_h and g_agg (so edge atomics accumulate onto h).
// ---------------------------------------------------------------------------
#define PREP_BLOCKS 128

__global__ void init_kernel(const float* __restrict__ x,
                            const float* __restrict__ gamma,
                            const float* __restrict__ beta,
                            const float* __restrict__ W1,
                            const float* __restrict__ W2,
                            const float* __restrict__ Wt) {
    if (blockIdx.x < PREP_BLOCKS) {
        int idx = blockIdx.x * blockDim.x + threadIdx.x;   // 0..32767
        {   int k = idx >> 8, n = idx & 255;
            g_w1h[n * 128 + k] = __float2half_rn(W1[idx]); }
        {   int kk = idx >> 7, n = idx & 127;
            g_w2h[n * 256 + kk] = __float2half_rn(W2[idx]); }
        if (idx < 16384) {
            int k = idx >> 7, n = idx & 127;
            g_wth[n * 128 + k] = __float2half_rn(Wt[idx]);
        }
        return;
    }

    int warp = ((blockIdx.x - PREP_BLOCKS) * blockDim.x + threadIdx.x) >> 5;
    int lane = threadIdx.x & 31;
    if (warp >= N_NODES) return;

    const float4* row = (const float4*)(x + (size_t)warp * EMBED);
    float4 v = row[lane];
    float s  = v.x + v.y + v.z + v.w;
    float ss = v.x * v.x + v.y * v.y + v.z * v.z + v.w * v.w;
    #pragma unroll
    for (int o = 16; o; o >>= 1) {
        s  += __shfl_xor_sync(0xFFFFFFFFu, s,  o);
        ss += __shfl_xor_sync(0xFFFFFFFFu, ss, o);
    }
    const float inv_d = 1.0f / (float)EMBED;
    float mu  = s * inv_d;
    float var = ss * inv_d - mu * mu;
    float inv = rsqrtf(var + LN_EPS);

    float4 g = ((const float4*)gamma)[lane];
    float4 b = ((const float4*)beta)[lane];
    float4 o4;
    o4.x = (v.x - mu) * inv * g.x + b.x;
    o4.y = (v.y - mu) * inv * g.y + b.y;
    o4.z = (v.z - mu) * inv * g.z + b.z;
    o4.w = (v.w - mu) * inv * g.w + b.w;
    ((float4*)(g_h + (size_t)warp * EMBED))[lane] = o4;
    ((float4*)(g_agg + (size_t)warp * EMBED))[lane] = o4;   // agg starts at h
}

// ---------------------------------------------------------------------------
// Kernel 2: fp16 mma.sync edge MLP. 128 edges/CTA, 8 warps, 2 CTAs/SM.
// Gather batched 4 rounds x 4 slots (12 loads in flight — measured optimum).
// ---------------------------------------------------------------------------
#define TE 128
#define ETH 256
#define A_STRIDE 264   // halves; 528B rows -> 16B-rotating, ldmatrix conflict-free
#define B_STRIDE 136   // halves; 272B rows

#define SM_CI   0
#define SM_NI   512
#define SM_B1   1024
#define SM_B2   2048
#define SM_A    2560
#define SM_B    (SM_A + 128 * A_STRIDE * 2)   // 70144
#define EDGE_SMEM (SM_B + 128 * B_STRIDE * 2) // 104960  -> 2 CTAs/SM

__device__ __forceinline__ void cp_tile(uint32_t sdst,
                                        const __half* __restrict__ src,
                                        int src_stride_halves, int tid) {
    #pragma unroll
    for (int i = tid; i < 2048; i += ETH) {
        int r = i >> 4, c = i & 15;
        cpa16(sdst + r * (B_STRIDE * 2) + c * 16,
              src + r * src_stride_halves + c * 8);
    }
}

__global__ __launch_bounds__(ETH, 2)
void edge_kernel(const float* __restrict__ eemb,
                 const int* __restrict__ eidx,
                 const float* __restrict__ b1g,
                 const float* __restrict__ b2g) {
    extern __shared__ char smem[];
    uint32_t sbase = smem_u32(smem);
    int tid = threadIdx.x, wid = tid >> 5, lane = tid & 31;
    int e0 = blockIdx.x * TE;

    int*   s_ci = (int*)(smem + SM_CI);
    int*   s_ni = (int*)(smem + SM_NI);
    float* sb1  = (float*)(smem + SM_B1);
    float* sb2  = (float*)(smem + SM_B2);

    cp_tile(sbase + SM_B, g_w1h, 128, tid); CP_COMMIT();

    if (tid < 128) {
        s_ci[tid] = eidx[e0 + tid];
        s_ni[tid] = eidx[N_EDGES + e0 + tid];
    }
    sb1[tid] = b1g[tid];
    if (tid < 128) sb2[tid] = b2g[tid];
    __syncthreads();

    // ---- gather: A1 = fp16(silu(e + h_c + h_n)), batched 4 rounds x 4 slots ----
    #pragma unroll
    for (int bt = 0; bt < 4; bt++) {
        float4 ee[4], hc[4], hn[4];
        int mm[4], cc[4];
        #pragma unroll
        for (int j = 0; j < 4; j++) {
            int v = tid + ETH * (bt * 4 + j);   // 0..4095
            mm[j] = v >> 5; cc[j] = v & 31;
            ee[j] = ((const float4*)(eemb + (size_t)(e0 + mm[j]) * EMBED))[cc[j]];
            hc[j] = ((const float4*)(g_h + (size_t)s_ci[mm[j]] * EMBED))[cc[j]];
            hn[j] = ((const float4*)(g_h + (size_t)s_ni[mm[j]] * EMBED))[cc[j]];
        }
        #pragma unroll
        for (int j = 0; j < 4; j++) {
            float s0 = silu_f(ee[j].x + hc[j].x + hn[j].x);
            float s1 = silu_f(ee[j].y + hc[j].y + hn[j].y);
            float s2 = silu_f(ee[j].z + hc[j].z + hn[j].z);
            float s3 = silu_f(ee[j].w + hc[j].w + hn[j].w);
            int off = (mm[j] * A_STRIDE + 4 * cc[j]) * 2;
            *(__half2*)(smem + SM_A + off)     = __floats2half2_rn(s0, s1);
            *(__half2*)(smem + SM_A + off + 4) = __floats2half2_rn(s2, s3);
        }
    }

    int rb = wid * 16;
    int ai = lane & 7, as_ = lane >> 3;
    int arow = rb + ai + (as_ & 1) * 8;
    int acolseg = (as_ >> 1) * 8;
    int bi = lane & 7, bs = (lane >> 3) & 1;
    int q = lane & 3;
    int r0 = rb + (lane >> 2), r1 = r0 + 8;

    // ================= GEMM1 (two n-halves) =================
    #pragma unroll 1
    for (int h = 0; h < 2; h++) {
        CP_WAIT(0);
        __syncthreads();

        float acc[16][4];
        #pragma unroll
        for (int i = 0; i < 16; i++)
            #pragma unroll
            for (int j = 0; j < 4; j++) acc[i][j] = 0.f;

        #pragma unroll
        for (int ks = 0; ks < 8; ks++) {
            uint32_t a4[4];
            uint32_t aoff = (uint32_t)(arow * A_STRIDE + ks * 16 + acolseg) * 2;
            ldm4(a4, sbase + SM_A + aoff);
            #pragma unroll
            for (int nt = 0; nt < 16; nt++) {
                uint32_t boff = (uint32_t)((nt * 8 + bi) * B_STRIDE + ks * 16 + bs * 8) * 2;
                uint32_t bw[2];
                ldm2(bw, sbase + SM_B + boff);
                mma_f16(acc[nt], a4, bw);
            }
        }
        __syncthreads();

        if (h == 0) { cp_tile(sbase + SM_B, g_w1h + 16384, 128, tid); CP_COMMIT(); }
        else        { cp_tile(sbase + SM_B, g_w2h,         256, tid); CP_COMMIT(); }

        int dbase = (h == 0) ? 128 : 0;
        #pragma unroll
        for (int nt = 0; nt < 16; nt++) {
            int c0 = nt * 8 + 2 * q;
            int gc = h * 128 + c0;
            float t0 = silu_f(acc[nt][0] + sb1[gc]);
            float t1 = silu_f(acc[nt][1] + sb1[gc + 1]);
            float t2 = silu_f(acc[nt][2] + sb1[gc]);
            float t3 = silu_f(acc[nt][3] + sb1[gc + 1]);
            int o0 = (r0 * A_STRIDE + dbase + c0) * 2;
            int o1 = (r1 * A_STRIDE + dbase + c0) * 2;
            *(__half2*)(smem + SM_A + o0) = __floats2half2_rn(t0, t1);
            *(__half2*)(smem + SM_A + o1) = __floats2half2_rn(t2, t3);
        }
    }

    // ================= GEMM2 (two k-phases) =============
    float acc2[16][4];
    #pragma unroll
    for (int i = 0; i < 16; i++)
        #pragma unroll
        for (int j = 0; j < 4; j++) acc2[i][j] = 0.f;

    #pragma unroll 1
    for (int ph = 0; ph < 2; ph++) {
        CP_WAIT(0);
        __syncthreads();

        int abase = (ph == 0) ? 128 : 0;
        #pragma unroll
        for (int ks = 0; ks < 8; ks++) {
            uint32_t a4[4];
            uint32_t aoff = (uint32_t)(arow * A_STRIDE + abase + ks * 16 + acolseg) * 2;
            ldm4(a4, sbase + SM_A + aoff);
            #pragma unroll
            for (int nt = 0; nt < 16; nt++) {
                uint32_t boff = (uint32_t)((nt * 8 + bi) * B_STRIDE + ks * 16 + bs * 8) * 2;
                uint32_t bw[2];
                ldm2(bw, sbase + SM_B + boff);
                mma_f16(acc2[nt], a4, bw);
            }
        }
        if (ph == 0) {
            __syncthreads();
            cp_tile(sbase + SM_B, g_w2h + 128, 256, tid); CP_COMMIT();
        }
    }

    // ---- epilogue ----
    {
        int ci0 = s_ci[r0], ci1 = s_ci[r1];
        int ni0 = s_ni[r0], ni1 = s_ni[r1];
        const float* hn0 = g_h + (size_t)ni0 * EMBED;
        const float* hn1 = g_h + (size_t)ni1 * EMBED;
        float* ag0 = g_agg + (size_t)ci0 * EMBED;
        float* ag1 = g_agg + (size_t)ci1 * EMBED;
        #pragma unroll
        for (int nt = 0; nt < 16; nt++) {
            int c0 = nt * 8 + 2 * q;
            float2 h0 = *(const float2*)(hn0 + c0);
            float2 h1 = *(const float2*)(hn1 + c0);
            atomicAdd(ag0 + c0,     (acc2[nt][0] + sb2[c0])     * h0.x);
            atomicAdd(ag0 + c0 + 1, (acc2[nt][1] + sb2[c0 + 1]) * h0.y);
            atomicAdd(ag1 + c0,     (acc2[nt][2] + sb2[c0])     * h1.x);
            atomicAdd(ag1 + c0 + 1, (acc2[nt][3] + sb2[c0 + 1]) * h1.y);
        }
    }
}

// ---------------------------------------------------------------------------
// Kernel 3: out = silu(g_agg) @ Wt + bt  — single 8-slot gather batch.
// ---------------------------------------------------------------------------
#define ONR 64
#define OSM_BT  0
#define OSM_A   512
#define OSM_B   (OSM_A + ONR * B_STRIDE * 2)    // 17920
#define OUT_SMEM (OSM_B + 128 * B_STRIDE * 2)   // 52736

__device__ __forceinline__ void cp_tile_full(uint32_t sdst,
                                             const __half* __restrict__ src,
                                             int src_stride_halves, int tid) {
    #pragma unroll
    for (int i = tid; i < 2048; i += 256) {
        int r = i >> 4, c = i & 15;
        cpa16(sdst + r * (B_STRIDE * 2) + c * 16,
              src + r * src_stride_halves + c * 8);
    }
}

__global__ __launch_bounds__(256, 4)
void out_kernel(const float* __restrict__ btg, float* __restrict__ out) {
    extern __shared__ char smem[];
    uint32_t sbase = smem_u32(smem);
    int tid = threadIdx.x, wid = tid >> 5, lane = tid & 31;
    int n0 = blockIdx.x * ONR;

    float* sbt = (float*)(smem + OSM_BT);

    cp_tile_full(sbase + OSM_B, g_wth, 128, tid); CP_COMMIT();
    if (tid < 128) sbt[tid] = btg[tid];

    // ---- gather: A = fp16(silu(agg)) — single batch of 8 loads (32 regs) ----
    {
        float4 av[8];
        #pragma unroll
        for (int j = 0; j < 8; j++) {
            int v = tid + 256 * j;   // 0..2047
            int m = v >> 5, c = v & 31;
            int row = n0 + m;
            av[j] = make_float4(0.f, 0.f, 0.f, 0.f);
            if (row < N_NODES)
                av[j] = ((const float4*)(g_agg + (size_t)row * EMBED))[c];
        }
        #pragma unroll
        for (int j = 0; j < 8; j++) {
            int v = tid + 256 * j;
            int m = v >> 5, c = v & 31;
            float s0 = silu_f(av[j].x);
            float s1 = silu_f(av[j].y);
            float s2 = silu_f(av[j].z);
            float s3 = silu_f(av[j].w);
            int off = (m * B_STRIDE + 4 * c) * 2;
            *(__half2*)(smem + OSM_A + off)     = __floats2half2_rn(s0, s1);
            *(__half2*)(smem + OSM_A + off + 4) = __floats2half2_rn(s2, s3);
        }
    }

    CP_WAIT(0);
    __syncthreads();

    int ai = lane & 7, as_ = lane >> 3;
    int arowoff = ai + (as_ & 1) * 8;
    int acolseg = (as_ >> 1) * 8;
    int bi = lane & 7, bs = (lane >> 3) & 1;
    int q = lane & 3;
    int nb = wid * 2;   // this warp's two n-tiles

    float acc[4][2][4];
    #pragma unroll
    for (int i = 0; i < 4; i++)
        #pragma unroll
        for (int t = 0; t < 2; t++)
            #pragma unroll
            for (int j = 0; j < 4; j++) acc[i][t][j] = 0.f;

    #pragma unroll
    for (int ks = 0; ks < 8; ks++) {
        uint32_t bw0[2], bw1[2];
        ldm2(bw0, sbase + OSM_B + (uint32_t)(((nb + 0) * 8 + bi) * B_STRIDE + ks * 16 + bs * 8) * 2);
        ldm2(bw1, sbase + OSM_B + (uint32_t)(((nb + 1) * 8 + bi) * B_STRIDE + ks * 16 + bs * 8) * 2);
        #pragma unroll
        for (int mb = 0; mb < 4; mb++) {
            uint32_t a4[4];
            uint32_t aoff = (uint32_t)((mb * 16 + arowoff) * B_STRIDE + ks * 16 + acolseg) * 2;
            ldm4(a4, sbase + OSM_A + aoff);
            mma_f16(acc[mb][0], a4, bw0);
            mma_f16(acc[mb][1], a4, bw1);
        }
    }

    #pragma unroll
    for (int mb = 0; mb < 4; mb++) {
        int row0 = n0 + mb * 16 + (lane >> 2);
        int row1 = row0 + 8;
        #pragma unroll
        for (int t = 0; t < 2; t++) {
            int c0 = (nb + t) * 8 + 2 * q;
            float2 b2 = *(const float2*)(sbt + c0);
            if (row0 < N_NODES) {
                float2 o0 = make_float2(acc[mb][t][0] + b2.x, acc[mb][t][1] + b2.y);
                *(float2*)(out + (size_t)row0 * EMBED + c0) = o0;
            }
            if (row1 < N_NODES) {
                float2 o1 = make_float2(acc[mb][t][2] + b2.x, acc[mb][t][3] + b2.y);
                *(float2*)(out + (size_t)row1 * EMBED + c0) = o1;
            }
        }
    }
}

// ---------------------------------------------------------------------------
extern "C" void kernel_launch(void* const* d_in, const int* in_sizes, int n_in,
                              void* d_out, int out_size) {
    const float* node  = (const float*)d_in[0];
    const float* eemb  = (const float*)d_in[1];
    const int*   eidx  = (const int*)  d_in[2];
    const float* gamma = (const float*)d_in[3];
    const float* beta  = (const float*)d_in[4];
    const float* W1    = (const float*)d_in[5];
    const float* b1    = (const float*)d_in[6];
    const float* W2    = (const float*)d_in[7];
    const float* b2    = (const float*)d_in[8];
    const float* Wt    = (const float*)d_in[9];
    const float* bt    = (const float*)d_in[10];
    float* out = (float*)d_out;

    cudaFuncSetAttribute(edge_kernel, cudaFuncAttributeMaxDynamicSharedMemorySize,
                         EDGE_SMEM);
    cudaFuncSetAttribute(out_kernel, cudaFuncAttributeMaxDynamicSharedMemorySize,
                         OUT_SMEM);

    init_kernel<<<PREP_BLOCKS + (N_NODES + 7) / 8, 256>>>(node, gamma, beta, W1, W2, Wt);
    edge_kernel<<<N_EDGES / TE, ETH, EDGE_SMEM>>>(eemb, eidx, b1, b2);
    out_kernel<<<(N_NODES + ONR - 1) / ONR, 256, OUT_SMEM>>>(bt, out);
}

// round 17
// speedup vs baseline: 1.0097x; 1.0016x over previous
#include <cuda_runtime.h>
#include <cuda_fp16.h>
#include <cstdint>

#define N_NODES 50000
#define EMBED 128
#define HIDDEN 256
#define N_EDGES 640000
#define LN_EPS 1e-5f

// ---------------- warp MMA / cp.async helpers (sm_80-class) ----------------
__device__ __forceinline__ uint32_t smem_u32(const void* p) {
    uint32_t a;
    asm("{ .reg .u64 t; cvta.to.shared.u64 t, %1; cvt.u32.u64 %0, t; }"
        : "=r"(a) : "l"(p));
    return a;
}
__device__ __forceinline__ void mma_f16(float* d, const uint32_t* a, const uint32_t* b) {
    asm volatile(
        "mma.sync.aligned.m16n8k16.row.col.f32.f16.f16.f32 "
        "{%0,%1,%2,%3}, {%4,%5,%6,%7}, {%8,%9}, {%0,%1,%2,%3};"
        : "+f"(d[0]), "+f"(d[1]), "+f"(d[2]), "+f"(d[3])
        : "r"(a[0]), "r"(a[1]), "r"(a[2]), "r"(a[3]), "r"(b[0]), "r"(b[1]));
}
__device__ __forceinline__ void ldm4(uint32_t* r, uint32_t addr) {
    asm volatile("ldmatrix.sync.aligned.m8n8.x4.shared.b16 {%0,%1,%2,%3}, [%4];"
                 : "=r"(r[0]), "=r"(r[1]), "=r"(r[2]), "=r"(r[3]) : "r"(addr));
}
__device__ __forceinline__ void ldm2(uint32_t* r, uint32_t addr) {
    asm volatile("ldmatrix.sync.aligned.m8n8.x2.shared.b16 {%0,%1}, [%2];"
                 : "=r"(r[0]), "=r"(r[1]) : "r"(addr));
}
__device__ __forceinline__ void cpa16(uint32_t dst, const void* src) {
    asm volatile("cp.async.cg.shared.global [%0], [%1], 16;" :: "r"(dst), "l"(src));
}
#define CP_COMMIT() asm volatile("cp.async.commit_group;" ::: "memory")
#define CP_WAIT(n)  asm volatile("cp.async.wait_group %0;" :: "n"(n) : "memory")

__device__ __forceinline__ float silu_f(float x) {
    return __fdividef(x, 1.0f + __expf(-x));
}

// ---------------- device scratch ----------------
__device__ float g_h[N_NODES * EMBED];     // layernormed node embeddings
__device__ float g_agg[N_NODES * EMBED];   // init to h; edge atomics add msg -> h+agg
__device__ __align__(16) __half g_w1h[32768];   // W1^T [n=256][k=128]
__device__ __align__(16) __half g_w2h[32768];   // W2^T [n=128][kk=256]
__device__ __align__(16) __half g_wth[16384];   // Wt^T [n=128][k=128]

// ---------------------------------------------------------------------------
// Kernel 1 (fused): blocks 0..127 = weight prep; rest = LayerNorm (warp/row).
// ln writes h into BOTH g_h and g_agg (so edge atomics accumulate onto h).
// ---------------------------------------------------------------------------
#define PREP_BLOCKS 128

__global__ void init_kernel(const float* __restrict__ x,
                            const float* __restrict__ gamma,
                            const float* __restrict__ beta,
                            const float* __restrict__ W1,
                            const float* __restrict__ W2,
                            const float* __restrict__ Wt) {
    if (blockIdx.x < PREP_BLOCKS) {
        int idx = blockIdx.x * blockDim.x + threadIdx.x;   // 0..32767
        {   int k = idx >> 8, n = idx & 255;
            g_w1h[n * 128 + k] = __float2half_rn(W1[idx]); }
        {   int kk = idx >> 7, n = idx & 127;
            g_w2h[n * 256 + kk] = __float2half_rn(W2[idx]); }
        if (idx < 16384) {
            int k = idx >> 7, n = idx & 127;
            g_wth[n * 128 + k] = __float2half_rn(Wt[idx]);
        }
        return;
    }

    int warp = ((blockIdx.x - PREP_BLOCKS) * blockDim.x + threadIdx.x) >> 5;
    int lane = threadIdx.x & 31;
    if (warp >= N_NODES) return;

    const float4* row = (const float4*)(x + (size_t)warp * EMBED);
    float4 v = row[lane];
    float s  = v.x + v.y + v.z + v.w;
    float ss = v.x * v.x + v.y * v.y + v.z * v.z + v.w * v.w;
    #pragma unroll
    for (int o = 16; o; o >>= 1) {
        s  += __shfl_xor_sync(0xFFFFFFFFu, s,  o);
        ss += __shfl_xor_sync(0xFFFFFFFFu, ss, o);
    }
    const float inv_d = 1.0f / (float)EMBED;
    float mu  = s * inv_d;
    float var = ss * inv_d - mu * mu;
    float inv = rsqrtf(var + LN_EPS);

    float4 g = ((const float4*)gamma)[lane];
    float4 b = ((const float4*)beta)[lane];
    float4 o4;
    o4.x = (v.x - mu) * inv * g.x + b.x;
    o4.y = (v.y - mu) * inv * g.y + b.y;
    o4.z = (v.z - mu) * inv * g.z + b.z;
    o4.w = (v.w - mu) * inv * g.w + b.w;
    ((float4*)(g_h + (size_t)warp * EMBED))[lane] = o4;
    ((float4*)(g_agg + (size_t)warp * EMBED))[lane] = o4;   // agg starts at h
}

// ---------------------------------------------------------------------------
// Kernel 2: fp16 mma.sync edge MLP. 128 edges/CTA, 8 warps, 2 CTAs/SM.
// Gather batched 4 rounds x 4 slots (12 loads in flight — measured optimum).
// ---------------------------------------------------------------------------
#define TE 128
#define ETH 256
#define A_STRIDE 264   // halves; 528B rows -> 16B-rotating, ldmatrix conflict-free
#define B_STRIDE 136   // halves; 272B rows

#define SM_CI   0
#define SM_NI   512
#define SM_B1   1024
#define SM_B2   2048
#define SM_A    2560
#define SM_B    (SM_A + 128 * A_STRIDE * 2)   // 70144
#define EDGE_SMEM (SM_B + 128 * B_STRIDE * 2) // 104960  -> 2 CTAs/SM

__device__ __forceinline__ void cp_tile(uint32_t sdst,
                                        const __half* __restrict__ src,
                                        int src_stride_halves, int tid) {
    #pragma unroll
    for (int i = tid; i < 2048; i += ETH) {
        int r = i >> 4, c = i & 15;
        cpa16(sdst + r * (B_STRIDE * 2) + c * 16,
              src + r * src_stride_halves + c * 8);
    }
}

__global__ __launch_bounds__(ETH, 2)
void edge_kernel(const float* __restrict__ eemb,
                 const int* __restrict__ eidx,
                 const float* __restrict__ b1g,
                 const float* __restrict__ b2g) {
    extern __shared__ char smem[];
    uint32_t sbase = smem_u32(smem);
    int tid = threadIdx.x, wid = tid >> 5, lane = tid & 31;
    int e0 = blockIdx.x * TE;

    int*   s_ci = (int*)(smem + SM_CI);
    int*   s_ni = (int*)(smem + SM_NI);
    float* sb1  = (float*)(smem + SM_B1);
    float* sb2  = (float*)(smem + SM_B2);

    cp_tile(sbase + SM_B, g_w1h, 128, tid); CP_COMMIT();

    if (tid < 128) {
        s_ci[tid] = eidx[e0 + tid];
        s_ni[tid] = eidx[N_EDGES + e0 + tid];
    }
    sb1[tid] = b1g[tid];
    if (tid < 128) sb2[tid] = b2g[tid];
    __syncthreads();

    // ---- gather: A1 = fp16(silu(e + h_c + h_n)), batched 4 rounds x 4 slots ----
    #pragma unroll
    for (int bt = 0; bt < 4; bt++) {
        float4 ee[4], hc[4], hn[4];
        int mm[4], cc[4];
        #pragma unroll
        for (int j = 0; j < 4; j++) {
            int v = tid + ETH * (bt * 4 + j);   // 0..4095
            mm[j] = v >> 5; cc[j] = v & 31;
            ee[j] = ((const float4*)(eemb + (size_t)(e0 + mm[j]) * EMBED))[cc[j]];
            hc[j] = ((const float4*)(g_h + (size_t)s_ci[mm[j]] * EMBED))[cc[j]];
            hn[j] = ((const float4*)(g_h + (size_t)s_ni[mm[j]] * EMBED))[cc[j]];
        }
        #pragma unroll
        for (int j = 0; j < 4; j++) {
            float s0 = silu_f(ee[j].x + hc[j].x + hn[j].x);
            float s1 = silu_f(ee[j].y + hc[j].y + hn[j].y);
            float s2 = silu_f(ee[j].z + hc[j].z + hn[j].z);
            float s3 = silu_f(ee[j].w + hc[j].w + hn[j].w);
            int off = (mm[j] * A_STRIDE + 4 * cc[j]) * 2;
            *(__half2*)(smem + SM_A + off)     = __floats2half2_rn(s0, s1);
            *(__half2*)(smem + SM_A + off + 4) = __floats2half2_rn(s2, s3);
        }
    }

    int rb = wid * 16;
    int ai = lane & 7, as_ = lane >> 3;
    int arow = rb + ai + (as_ & 1) * 8;
    int acolseg = (as_ >> 1) * 8;
    int bi = lane & 7, bs = (lane >> 3) & 1;
    int q = lane & 3;
    int r0 = rb + (lane >> 2), r1 = r0 + 8;

    // ================= GEMM1 (two n-halves) =================
    #pragma unroll 1
    for (int h = 0; h < 2; h++) {
        CP_WAIT(0);
        __syncthreads();

        float acc[16][4];
        #pragma unroll
        for (int i = 0; i < 16; i++)
            #pragma unroll
            for (int j = 0; j < 4; j++) acc[i][j] = 0.f;

        #pragma unroll
        for (int ks = 0; ks < 8; ks++) {
            uint32_t a4[4];
            uint32_t aoff = (uint32_t)(arow * A_STRIDE + ks * 16 + acolseg) * 2;
            ldm4(a4, sbase + SM_A + aoff);
            #pragma unroll
            for (int nt = 0; nt < 16; nt++) {
                uint32_t boff = (uint32_t)((nt * 8 + bi) * B_STRIDE + ks * 16 + bs * 8) * 2;
                uint32_t bw[2];
                ldm2(bw, sbase + SM_B + boff);
                mma_f16(acc[nt], a4, bw);
            }
        }
        __syncthreads();

        if (h == 0) { cp_tile(sbase + SM_B, g_w1h + 16384, 128, tid); CP_COMMIT(); }
        else        { cp_tile(sbase + SM_B, g_w2h,         256, tid); CP_COMMIT(); }

        int dbase = (h == 0) ? 128 : 0;
        #pragma unroll
        for (int nt = 0; nt < 16; nt++) {
            int c0 = nt * 8 + 2 * q;
            int gc = h * 128 + c0;
            float t0 = silu_f(acc[nt][0] + sb1[gc]);
            float t1 = silu_f(acc[nt][1] + sb1[gc + 1]);
            float t2 = silu_f(acc[nt][2] + sb1[gc]);
            float t3 = silu_f(acc[nt][3] + sb1[gc + 1]);
            int o0 = (r0 * A_STRIDE + dbase + c0) * 2;
            int o1 = (r1 * A_STRIDE + dbase + c0) * 2;
            *(__half2*)(smem + SM_A + o0) = __floats2half2_rn(t0, t1);
            *(__half2*)(smem + SM_A + o1) = __floats2half2_rn(t2, t3);
        }
    }

    // ================= GEMM2 (two k-phases) =============
    float acc2[16][4];
    #pragma unroll
    for (int i = 0; i < 16; i++)
        #pragma unroll
        for (int j = 0; j < 4; j++) acc2[i][j] = 0.f;

    #pragma unroll 1
    for (int ph = 0; ph < 2; ph++) {
        CP_WAIT(0);
        __syncthreads();

        int abase = (ph == 0) ? 128 : 0;
        #pragma unroll
        for (int ks = 0; ks < 8; ks++) {
            uint32_t a4[4];
            uint32_t aoff = (uint32_t)(arow * A_STRIDE + abase + ks * 16 + acolseg) * 2;
            ldm4(a4, sbase + SM_A + aoff);
            #pragma unroll
            for (int nt = 0; nt < 16; nt++) {
                uint32_t boff = (uint32_t)((nt * 8 + bi) * B_STRIDE + ks * 16 + bs * 8) * 2;
                uint32_t bw[2];
                ldm2(bw, sbase + SM_B + boff);
                mma_f16(acc2[nt], a4, bw);
            }
        }
        if (ph == 0) {
            __syncthreads();
            cp_tile(sbase + SM_B, g_w2h + 128, 256, tid); CP_COMMIT();
        }
    }

    // ---- epilogue ----
    {
        int ci0 = s_ci[r0], ci1 = s_ci[r1];
        int ni0 = s_ni[r0], ni1 = s_ni[r1];
        const float* hn0 = g_h + (size_t)ni0 * EMBED;
        const float* hn1 = g_h + (size_t)ni1 * EMBED;
        float* ag0 = g_agg + (size_t)ci0 * EMBED;
        float* ag1 = g_agg + (size_t)ci1 * EMBED;
        #pragma unroll
        for (int nt = 0; nt < 16; nt++) {
            int c0 = nt * 8 + 2 * q;
            float2 h0 = *(const float2*)(hn0 + c0);
            float2 h1 = *(const float2*)(hn1 + c0);
            atomicAdd(ag0 + c0,     (acc2[nt][0] + sb2[c0])     * h0.x);
            atomicAdd(ag0 + c0 + 1, (acc2[nt][1] + sb2[c0 + 1]) * h0.y);
            atomicAdd(ag1 + c0,     (acc2[nt][2] + sb2[c0])     * h1.x);
            atomicAdd(ag1 + c0 + 1, (acc2[nt][3] + sb2[c0 + 1]) * h1.y);
        }
    }
}

// ---------------------------------------------------------------------------
// Kernel 3: out = silu(g_agg) @ Wt + bt  (2-round x 4-slot gather, 4 CTAs/SM)
// ---------------------------------------------------------------------------
#define ONR 64
#define OSM_BT  0
#define OSM_A   512
#define OSM_B   (OSM_A + ONR * B_STRIDE * 2)    // 17920
#define OUT_SMEM (OSM_B + 128 * B_STRIDE * 2)   // 52736

__device__ __forceinline__ void cp_tile_full(uint32_t sdst,
                                             const __half* __restrict__ src,
                                             int src_stride_halves, int tid) {
    #pragma unroll
    for (int i = tid; i < 2048; i += 256) {
        int r = i >> 4, c = i & 15;
        cpa16(sdst + r * (B_STRIDE * 2) + c * 16,
              src + r * src_stride_halves + c * 8);
    }
}

__global__ __launch_bounds__(256, 4)
void out_kernel(const float* __restrict__ btg, float* __restrict__ out) {
    extern __shared__ char smem[];
    uint32_t sbase = smem_u32(smem);
    int tid = threadIdx.x, wid = tid >> 5, lane = tid & 31;
    int n0 = blockIdx.x * ONR;

    float* sbt = (float*)(smem + OSM_BT);

    cp_tile_full(sbase + OSM_B, g_wth, 128, tid); CP_COMMIT();
    if (tid < 128) sbt[tid] = btg[tid];

    #pragma unroll
    for (int bt = 0; bt < 2; bt++) {
        float4 av[4];
        int mm[4], cc[4];
        #pragma unroll
        for (int j = 0; j < 4; j++) {
            int v = tid + 256 * (bt * 4 + j);   // 0..2047
            mm[j] = v >> 5; cc[j] = v & 31;
            int row = n0 + mm[j];
            av[j] = make_float4(0.f, 0.f, 0.f, 0.f);
            if (row < N_NODES)
                av[j] = ((const float4*)(g_agg + (size_t)row * EMBED))[cc[j]];
        }
        #pragma unroll
        for (int j = 0; j < 4; j++) {
            float s0 = silu_f(av[j].x);
            float s1 = silu_f(av[j].y);
            float s2 = silu_f(av[j].z);
            float s3 = silu_f(av[j].w);
            int off = (mm[j] * B_STRIDE + 4 * cc[j]) * 2;
            *(__half2*)(smem + OSM_A + off)     = __floats2half2_rn(s0, s1);
            *(__half2*)(smem + OSM_A + off + 4) = __floats2half2_rn(s2, s3);
        }
    }

    CP_WAIT(0);
    __syncthreads();

    int ai = lane & 7, as_ = lane >> 3;
    int arowoff = ai + (as_ & 1) * 8;
    int acolseg = (as_ >> 1) * 8;
    int bi = lane & 7, bs = (lane >> 3) & 1;
    int q = lane & 3;
    int nb = wid * 2;   // this warp's two n-tiles

    float acc[4][2][4];
    #pragma unroll
    for (int i = 0; i < 4; i++)
        #pragma unroll
        for (int t = 0; t < 2; t++)
            #pragma unroll
            for (int j = 0; j < 4; j++) acc[i][t][j] = 0.f;

    #pragma unroll
    for (int ks = 0; ks < 8; ks++) {
        uint32_t bw0[2], bw1[2];
        ldm2(bw0, sbase + OSM_B + (uint32_t)(((nb + 0) * 8 + bi) * B_STRIDE + ks * 16 + bs * 8) * 2);
        ldm2(bw1, sbase + OSM_B + (uint32_t)(((nb + 1) * 8 + bi) * B_STRIDE + ks * 16 + bs * 8) * 2);
        #pragma unroll
        for (int mb = 0; mb < 4; mb++) {
            uint32_t a4[4];
            uint32_t aoff = (uint32_t)((mb * 16 + arowoff) * B_STRIDE + ks * 16 + acolseg) * 2;
            ldm4(a4, sbase + OSM_A + aoff);
            mma_f16(acc[mb][0], a4, bw0);
            mma_f16(acc[mb][1], a4, bw1);
        }
    }

    #pragma unroll
    for (int mb = 0; mb < 4; mb++) {
        int row0 = n0 + mb * 16 + (lane >> 2);
        int row1 = row0 + 8;
        #pragma unroll
        for (int t = 0; t < 2; t++) {
            int c0 = (nb + t) * 8 + 2 * q;
            float2 b2 = *(const float2*)(sbt + c0);
            if (row0 < N_NODES) {
                float2 o0 = make_float2(acc[mb][t][0] + b2.x, acc[mb][t][1] + b2.y);
                *(float2*)(out + (size_t)row0 * EMBED + c0) = o0;
            }
            if (row1 < N_NODES) {
                float2 o1 = make_float2(acc[mb][t][2] + b2.x, acc[mb][t][3] + b2.y);
                *(float2*)(out + (size_t)row1 * EMBED + c0) = o1;
            }
        }
    }
}

// ---------------------------------------------------------------------------
extern "C" void kernel_launch(void* const* d_in, const int* in_sizes, int n_in,
                              void* d_out, int out_size) {
    const float* node  = (const float*)d_in[0];
    const float* eemb  = (const float*)d_in[1];
    const int*   eidx  = (const int*)  d_in[2];
    const float* gamma = (const float*)d_in[3];
    const float* beta  = (const float*)d_in[4];
    const float* W1    = (const float*)d_in[5];
    const float* b1    = (const float*)d_in[6];
    const float* W2    = (const float*)d_in[7];
    const float* b2    = (const float*)d_in[8];
    const float* Wt    = (const float*)d_in[9];
    const float* bt    = (const float*)d_in[10];
    float* out = (float*)d_out;

    cudaFuncSetAttribute(edge_kernel, cudaFuncAttributeMaxDynamicSharedMemorySize,
                         EDGE_SMEM);
    cudaFuncSetAttribute(out_kernel, cudaFuncAttributeMaxDynamicSharedMemorySize,
                         OUT_SMEM);

    init_kernel<<<PREP_BLOCKS + (N_NODES + 7) / 8, 256>>>(node, gamma, beta, W1, W2, Wt);
    edge_kernel<<<N_EDGES / TE, ETH, EDGE_SMEM>>>(eemb, eidx, b1, b2);
    out_kernel<<<(N_NODES + ONR - 1) / ONR, 256, OUT_SMEM>>>(bt, out);
}